// round 3
// baseline (speedup 1.0000x reference)
#include <cuda_runtime.h>
#include <math.h>

#define LRW 256
#define LRH 256
#define HRW 1024
#define HRH 1024
#define NC 3
#define RAD 4

#define LRN (NC * LRH * LRW)

// Scratch (no cudaMalloc allowed) — device globals.
__device__ float g_A[LRN];
__device__ float g_B[LRN];

// ---------------------------------------------------------------------------
// Helpers
// ---------------------------------------------------------------------------
__device__ __forceinline__ void load12(float* v, const float* base) {
    float4 q0 = *reinterpret_cast<const float4*>(base);
    float4 q1 = *reinterpret_cast<const float4*>(base + 4);
    float4 q2 = *reinterpret_cast<const float4*>(base + 8);
    v[0]=q0.x; v[1]=q0.y; v[2]=q0.z;  v[3]=q0.w;
    v[4]=q1.x; v[5]=q1.y; v[6]=q1.z;  v[7]=q1.w;
    v[8]=q2.x; v[9]=q2.y; v[10]=q2.z; v[11]=q2.w;
}

// h[i] = sum v[i..i+4], i = 0..7  (sliding 5-window)
__device__ __forceinline__ void hsum5(float* h, const float* v) {
    h[0] = v[0] + v[1] + v[2] + v[3] + v[4];
#pragma unroll
    for (int i = 1; i < 8; ++i) h[i] = h[i - 1] - v[i - 1] + v[i + 4];
}

// ---------------------------------------------------------------------------
// Fused low-res kernel (unchanged from round 2): tile 32x32, 256 threads.
// ---------------------------------------------------------------------------
#define LTS 32
#define LEX 40
#define LSP 44

__global__ void __launch_bounds__(256) lr_fused(const float* __restrict__ lrx,
                                                const float* __restrict__ lry,
                                                const float* __restrict__ boxw) {
    __shared__ __align__(16) float Xs[LEX * LSP];
    __shared__ __align__(16) float Ys[LEX * LSP];
    __shared__ __align__(16) float Vx[LTS * LSP];
    __shared__ __align__(16) float Vy[LTS * LSP];
    __shared__ __align__(16) float Vxy[LTS * LSP];
    __shared__ __align__(16) float Vxx[LTS * LSP];

    const int c = blockIdx.z;
    const int x0t = blockIdx.x * LTS;
    const int y0t = blockIdx.y * LTS;
    const int tid = threadIdx.x;
    const float* __restrict__ px = lrx + c * LRH * LRW;
    const float* __restrict__ py = lry + c * LRH * LRW;

    for (int j = tid; j < LEX * LEX; j += 256) {
        int ly = j / LEX, lx = j % LEX;
        int Y = y0t - RAD + ly; Y = Y < 0 ? 0 : (Y > LRH - 1 ? LRH - 1 : Y);
        int X = x0t - RAD + lx; X = X < 0 ? 0 : (X > LRW - 1 ? LRW - 1 : X);
        Xs[ly * LSP + lx] = px[Y * LRW + X];
        Ys[ly * LSP + lx] = py[Y * LRW + X];
    }
    __syncthreads();

    for (int j = tid; j < LTS * LEX; j += 256) {
        int ry = j / LEX, lx = j % LEX;
        float sx = 0.f, sy = 0.f, sxy = 0.f, sxx = 0.f;
#pragma unroll
        for (int k = 0; k < 9; ++k) {
            float vx = Xs[(ry + k) * LSP + lx];
            float vy = Ys[(ry + k) * LSP + lx];
            sx += vx; sy += vy; sxy += vx * vy; sxx += vx * vx;
        }
        Vx[ry * LSP + lx] = sx;  Vy[ry * LSP + lx] = sy;
        Vxy[ry * LSP + lx] = sxy; Vxx[ry * LSP + lx] = sxx;
    }
    __syncthreads();

    const int ty = tid >> 3;
    const int x0 = (tid & 7) << 2;
    float vx[12], vy[12], vxy[12], vxx[12];
    load12(vx,  &Vx[ty * LSP + x0]);
    load12(vy,  &Vy[ty * LSP + x0]);
    load12(vxy, &Vxy[ty * LSP + x0]);
    load12(vxx, &Vxx[ty * LSP + x0]);

    float hx[4], hy[4], hxy[4], hxx[4];
    hx[0] = vx[0]+vx[1]+vx[2]+vx[3]+vx[4]+vx[5]+vx[6]+vx[7]+vx[8];
    hy[0] = vy[0]+vy[1]+vy[2]+vy[3]+vy[4]+vy[5]+vy[6]+vy[7]+vy[8];
    hxy[0]= vxy[0]+vxy[1]+vxy[2]+vxy[3]+vxy[4]+vxy[5]+vxy[6]+vxy[7]+vxy[8];
    hxx[0]= vxx[0]+vxx[1]+vxx[2]+vxx[3]+vxx[4]+vxx[5]+vxx[6]+vxx[7]+vxx[8];
#pragma unroll
    for (int i = 1; i < 4; ++i) {
        hx[i]  = hx[i-1]  - vx[i-1]  + vx[i+8];
        hy[i]  = hy[i-1]  - vy[i-1]  + vy[i+8];
        hxy[i] = hxy[i-1] - vxy[i-1] + vxy[i+8];
        hxx[i] = hxx[i-1] - vxx[i-1] + vxx[i+8];
    }

    const float w = boxw[c * 81];
    float A_[4], B_[4];
#pragma unroll
    for (int p = 0; p < 4; ++p) {
        float mx = hx[p] * w, my = hy[p] * w, mxy = hxy[p] * w, mxx = hxx[p] * w;
        float A = (mxy - mx * my) / (mxx - mx * mx + 2.0f);   // EPS = 2
        A_[p] = A; B_[p] = my - A * mx;
    }
    int o = c * LRH * LRW + (y0t + ty) * LRW + (x0t + x0);
    *reinterpret_cast<float4*>(&g_A[o]) = make_float4(A_[0], A_[1], A_[2], A_[3]);
    *reinterpret_cast<float4*>(&g_B[o]) = make_float4(B_[0], B_[1], B_[2], B_[3]);
}

// ---------------------------------------------------------------------------
// High-res fused kernel, separable version.
// Setup: per-block coord tables (x: ix/fx; rows: iy/fy; vertical 5-sum
//        weights over <=3 LR rows per output row).
// HL pass: horizontal-only bilinear of ~13 LR rows at 40 HR columns.
// T pass : vertical 5-sums computed directly as weighted sums of HL rows.
// Stage 3: 4 px/thread; top/bot sums from T, center row lerped from HL.
// ---------------------------------------------------------------------------
#define TS 32
#define HALO 4
#define EX 40
#define SP 44
#define HLROWS 13
#define TROWS 36

__global__ void __launch_bounds__(256, 3) hr_stencil(const float* __restrict__ hrx,
                                                     float* __restrict__ out) {
    __shared__ __align__(16) float HLA[HLROWS * SP];
    __shared__ __align__(16) float HLB[HLROWS * SP];
    __shared__ __align__(16) float TA[TROWS * SP];
    __shared__ __align__(16) float TB[TROWS * SP];
    __shared__ int   s_ix[EX];
    __shared__ float s_fx[EX];
    __shared__ int   s_riy[EX];   // local (jbase-relative) LR row of ext row r
    __shared__ float s_rfy[EX];
    __shared__ int   s_j0[TROWS]; // local base LR row for T window
    __shared__ __align__(16) float4 s_w[TROWS];

    const int c = blockIdx.z;
    const int tx0 = blockIdx.x * TS;
    const int ty0 = blockIdx.y * TS;
    const int tid = threadIdx.x;
    const float sc = 255.0f / 1023.0f;   // (src-1)/(out-1), align_corners

    const float* __restrict__ gA = g_A + c * LRH * LRW;
    const float* __restrict__ gB = g_B + c * LRH * LRW;

    int Yb = ty0 - HALO; Yb = Yb < 0 ? 0 : Yb;
    int jbase = (int)floorf((float)Yb * sc);
    if (jbase > LRH - 2) jbase = LRH - 2;

    // ---- coord / weight tables ----
    if (tid < EX) {                       // x columns
        int X = tx0 - HALO + tid; X = X < 0 ? 0 : (X > HRW - 1 ? HRW - 1 : X);
        float t = (float)X * sc;
        int ix = (int)floorf(t); if (ix > LRW - 2) ix = LRW - 2;
        s_ix[tid] = ix; s_fx[tid] = t - (float)ix;
    } else if (tid < 2 * EX) {            // ext rows
        int r = tid - EX;
        int Y = ty0 - HALO + r; Y = Y < 0 ? 0 : (Y > HRH - 1 ? HRH - 1 : Y);
        float t = (float)Y * sc;
        int iy = (int)floorf(t); if (iy > LRH - 2) iy = LRH - 2;
        s_riy[r] = iy - jbase; s_rfy[r] = t - (float)iy;
    } else if (tid < 2 * EX + TROWS) {    // vertical 5-sum weights
        int ry = tid - 2 * EX;
        float w0 = 0.f, w1 = 0.f, w2 = 0.f, w3 = 0.f;
        int j0 = 0;
#pragma unroll
        for (int k = 0; k < 5; ++k) {
            int Y = ty0 - HALO + ry + k; Y = Y < 0 ? 0 : (Y > HRH - 1 ? HRH - 1 : Y);
            float t = (float)Y * sc;
            int iy = (int)floorf(t); if (iy > LRH - 2) iy = LRH - 2;
            float fy = t - (float)iy;
            if (k == 0) j0 = iy;
            int d = iy - j0;
            w0 += (d == 0) ? (1.0f - fy) : 0.0f;
            w1 += (d == 0) ? fy : ((d == 1) ? (1.0f - fy) : 0.0f);
            w2 += (d == 1) ? fy : ((d == 2) ? (1.0f - fy) : 0.0f);
            w3 += (d == 2) ? fy : 0.0f;
        }
        s_j0[ry] = j0 - jbase;
        s_w[ry] = make_float4(w0, w1, w2, w3);
    }
    __syncthreads();

    // ---- HL pass: horizontal bilinear of LR rows at HR columns ----
    if (tid < 240) {
        int part = tid / 40, col = tid - part * 40;
        int fld = part >= 3 ? 1 : 0;
        int p3 = part - fld * 3;
        int rb = p3 * 5;
        int rc = (p3 == 2) ? (HLROWS - 10) : 5;
        const float* __restrict__ gF = fld ? gB : gA;
        float* __restrict__ HF = fld ? HLB : HLA;
        int ix = s_ix[col]; float fx = s_fx[col]; float ofx = 1.0f - fx;
        for (int j = rb; j < rb + rc; ++j) {
            int lr = jbase + j; if (lr > LRH - 1) lr = LRH - 1;
            const float* p = gF + lr * LRW + ix;
            HF[j * SP + col] = p[0] * ofx + p[1] * fx;
        }
    }
    __syncthreads();

    // ---- T pass: vertical 5-sums as weighted HL-row sums ----
    if (tid < 240) {
        int part = tid / 40, col = tid - part * 40;
        int fld = part >= 3 ? 1 : 0;
        int p3 = part - fld * 3;
        int rb = p3 * 12;
        const float* __restrict__ HF = fld ? HLB : HLA;
        float* __restrict__ TF = fld ? TB : TA;
#pragma unroll
        for (int q = 0; q < 12; ++q) {
            int ry = rb + q;
            int j0 = s_j0[ry];
            float4 w = s_w[ry];
            const float* h = HF + j0 * SP + col;
            TF[ry * SP + col] =
                h[0] * w.x + h[SP] * w.y + h[2 * SP] * w.z + h[3 * SP] * w.w;
        }
    }
    __syncthreads();

    // ---- Stage 3: 4 consecutive output px per thread ----
    const int ty = tid >> 3;            // output row 0..31
    const int x0 = (tid & 7) << 2;      // output col base 0..28

    float vAt[12], vAb[12], vBt[12], vBb[12];
    load12(vAt, &TA[ty * SP + x0]);
    load12(vAb, &TA[(ty + 4) * SP + x0]);
    load12(vBt, &TB[ty * SP + x0]);
    load12(vBb, &TB[(ty + 4) * SP + x0]);

    // center row (ext row ty+4) lerped from HL
    const int jc = s_riy[ty + 4];
    const float fyc = s_rfy[ty + 4], ofy = 1.0f - fyc;
    float vAc[12], vBc[12];
    {
        float a0[12], a1[12];
        load12(a0, &HLA[jc * SP + x0]);
        load12(a1, &HLA[(jc + 1) * SP + x0]);
#pragma unroll
        for (int i = 0; i < 12; ++i) vAc[i] = a0[i] * ofy + a1[i] * fyc;
        load12(a0, &HLB[jc * SP + x0]);
        load12(a1, &HLB[(jc + 1) * SP + x0]);
#pragma unroll
        for (int i = 0; i < 12; ++i) vBc[i] = a0[i] * ofy + a1[i] * fyc;
    }

    float hAt[8], hAb[8], hAc[8], hBt[8], hBb[8], hBc[8];
    hsum5(hAt, vAt); hsum5(hAb, vAb); hsum5(hAc, vAc);
    hsum5(hBt, vBt); hsum5(hBb, vBb); hsum5(hBc, vBc);

    const int Y = ty0 + ty;
    const float4 im4 = *reinterpret_cast<const float4*>(
        &hrx[(c * HRH + Y) * HRW + tx0 + x0]);
    const float imv[4] = {im4.x, im4.y, im4.z, im4.w};

    const float i45 = 1.0f / 45.0f, i25 = 1.0f / 25.0f;
    float res[4];
#pragma unroll
    for (int p = 0; p < 4; ++p) {
        float atl = hAt[p], atr = hAt[p + 4];
        float abl = hAb[p], abr = hAb[p + 4];
        float acl = hAc[p], acr = hAc[p + 4];
        float btl = hBt[p], btr = hBt[p + 4];
        float bbl = hBb[p], bbr = hBb[p + 4];
        float bcl = hBc[p], bcr = hBc[p + 4];
        float atc = vAt[p + 4], abc = vAb[p + 4];
        float btc = vBt[p + 4], bbc = vBb[p + 4];

        float cA[8], cB[8];
        cA[0] = (atl + abl - acl) * i45;  cB[0] = (btl + bbl - bcl) * i45;  // L
        cA[1] = (atr + abr - acr) * i45;  cB[1] = (btr + bbr - bcr) * i45;  // R
        cA[2] = (atl + atr - atc) * i45;  cB[2] = (btl + btr - btc) * i45;  // U
        cA[3] = (abl + abr - abc) * i45;  cB[3] = (bbl + bbr - bbc) * i45;  // D
        cA[4] = atl * i25;                cB[4] = btl * i25;                // NW
        cA[5] = atr * i25;                cB[5] = btr * i25;                // NE
        cA[6] = abl * i25;                cB[6] = bbl * i25;                // SW
        cA[7] = abr * i25;                cB[7] = bbr * i25;                // SE

        const float im = imv[p];
        float best = cA[0] * im + cB[0] - im;
        float bestA = fabsf(best);
#pragma unroll
        for (int k = 1; k < 8; ++k) {
            float d = cA[k] * im + cB[k] - im;
            float ad = fabsf(d);
            if (ad < bestA) { bestA = ad; best = d; }  // strict '<' = first-min
        }
        float r = truncf(best + im);
        res[p] = fminf(fmaxf(r, 0.0f), 255.0f);
    }
    *reinterpret_cast<float4*>(&out[(c * HRH + Y) * HRW + tx0 + x0]) =
        make_float4(res[0], res[1], res[2], res[3]);
}

// ---------------------------------------------------------------------------
extern "C" void kernel_launch(void* const* d_in, const int* in_sizes, int n_in,
                              void* d_out, int out_size) {
    const float* lrx  = (const float*)d_in[0];
    const float* lry  = (const float*)d_in[1];
    const float* hrx  = (const float*)d_in[2];
    const float* boxw = (const float*)d_in[3];
    float* out = (float*)d_out;

    dim3 lgrid(LRW / LTS, LRH / LTS, NC);
    lr_fused<<<lgrid, 256>>>(lrx, lry, boxw);

    dim3 grid(HRW / TS, HRH / TS, NC);
    hr_stencil<<<grid, 256>>>(hrx, out);
}